// round 4
// baseline (speedup 1.0000x reference)
#include <cuda_runtime.h>

// ---------------------------------------------------------------------------
// 3-layer GRU + linear head. B=64, T=512, F=128, H=512, 3H=1536, O=128.
// ---------------------------------------------------------------------------
#define B_SZ   64
#define T_SZ   512
#define F_SZ   128
#define H_SZ   512
#define G3_SZ  1536
#define O_SZ   128
#define M_SZ   (B_SZ * T_SZ)

#define SCAN_NBLK  128
#define GRP_BLKS   32
#define CNT_PER_LAUNCH (T_SZ * GRP_BLKS)   // 16384 (power of two)

typedef unsigned long long u64;

__device__ __forceinline__ u64 splat2(float x) {
    u64 r; asm("mov.b64 %0, {%1, %1};" : "=l"(r) : "f"(x)); return r;
}
__device__ __forceinline__ void fma2(u64 &d, u64 a, u64 b) {
    asm("fma.rn.f32x2 %0, %1, %2, %0;" : "+l"(d) : "l"(a), "l"(b));
}
__device__ __forceinline__ float2 unpack2(u64 v) {
    float2 f; asm("mov.b64 {%0, %1}, %2;" : "=f"(f.x), "=f"(f.y) : "l"(v)); return f;
}
__device__ __forceinline__ unsigned ld_acq(const unsigned* p) {
    unsigned v; asm volatile("ld.global.acquire.gpu.u32 %0, [%1];" : "=r"(v) : "l"(p) : "memory"); return v;
}
__device__ __forceinline__ unsigned atom_inc_acqrel(unsigned* p) {
    unsigned r; asm volatile("atom.add.acq_rel.gpu.global.u32 %0, [%1], 1;" : "=r"(r) : "l"(p) : "memory"); return r;
}
__device__ __forceinline__ void red_inc_release(unsigned* p) {
    asm volatile("red.add.release.gpu.global.u32 [%0], 1;" :: "l"(p) : "memory");
}

// ---------------------------------------------------------------------------
// Scratch (device globals -- allocation-free per harness rules)
// ---------------------------------------------------------------------------
__device__ float    g_xp[(size_t)M_SZ * G3_SZ];
__device__ float    g_hseq[(size_t)M_SZ * H_SZ];
__device__ unsigned g_cnt4[4 * 32];
__device__ unsigned g_gen4[4 * 32];

// ---------------------------------------------------------------------------
// GEMM: C[M,N] = A[M,K] @ W[N,K]^T + bias[N].  128x128x16 tile, f32x2 FMA,
// register double-buffered gmem loads.
// ---------------------------------------------------------------------------
__global__ void __launch_bounds__(256)
gemm_bias_kernel(const float* __restrict__ A, const float* __restrict__ W,
                 const float* __restrict__ bias, float* __restrict__ C,
                 int M, int N, int K)
{
    __shared__ float As[16][132];
    __shared__ float Ws[16][132];

    const int tid = threadIdx.x;
    const int tx  = tid & 15;
    const int ty  = tid >> 4;
    const int m0  = blockIdx.y * 128;
    const int n0  = blockIdx.x * 128;

    u64 acc[8][4];
#pragma unroll
    for (int i = 0; i < 8; i++)
#pragma unroll
        for (int j = 0; j < 4; j++) acc[i][j] = 0ull;

    const int lr = tid >> 2;
    const int lk = (tid & 3) * 4;

    float4 pa[2], pw[2];
#pragma unroll
    for (int h = 0; h < 2; h++) {
        const int row = lr + h * 64;
        pa[h] = *(const float4*)(A + (size_t)(m0 + row) * K + lk);
        pw[h] = *(const float4*)(W + (size_t)(n0 + row) * K + lk);
    }

    for (int k0 = 0; k0 < K; k0 += 16) {
#pragma unroll
        for (int h = 0; h < 2; h++) {
            const int row = lr + h * 64;
            As[lk + 0][row] = pa[h].x; As[lk + 1][row] = pa[h].y;
            As[lk + 2][row] = pa[h].z; As[lk + 3][row] = pa[h].w;
            Ws[lk + 0][row] = pw[h].x; Ws[lk + 1][row] = pw[h].y;
            Ws[lk + 2][row] = pw[h].z; Ws[lk + 3][row] = pw[h].w;
        }
        __syncthreads();
        if (k0 + 16 < K) {
#pragma unroll
            for (int h = 0; h < 2; h++) {
                const int row = lr + h * 64;
                pa[h] = *(const float4*)(A + (size_t)(m0 + row) * K + k0 + 16 + lk);
                pw[h] = *(const float4*)(W + (size_t)(n0 + row) * K + k0 + 16 + lk);
            }
        }
#pragma unroll
        for (int k = 0; k < 16; k++) {
            float4 a0 = *(const float4*)&As[k][ty * 8];
            float4 a1 = *(const float4*)&As[k][ty * 8 + 4];
            ulonglong2 w01 = *(const ulonglong2*)&Ws[k][tx * 8];
            ulonglong2 w23 = *(const ulonglong2*)&Ws[k][tx * 8 + 4];
            float av[8] = {a0.x, a0.y, a0.z, a0.w, a1.x, a1.y, a1.z, a1.w};
#pragma unroll
            for (int i = 0; i < 8; i++) {
                u64 as = splat2(av[i]);
                fma2(acc[i][0], as, w01.x);
                fma2(acc[i][1], as, w01.y);
                fma2(acc[i][2], as, w23.x);
                fma2(acc[i][3], as, w23.y);
            }
        }
        __syncthreads();
    }

#pragma unroll
    for (int i = 0; i < 8; i++) {
        const int m = m0 + ty * 8 + i;
        float* crow = C + (size_t)m * N + n0 + tx * 8;
#pragma unroll
        for (int j = 0; j < 4; j++) {
            float2 v = unpack2(acc[i][j]);
            const int n = n0 + tx * 8 + j * 2;
            crow[j * 2 + 0] = v.x + bias[n + 0];
            crow[j * 2 + 1] = v.y + bias[n + 1];
        }
    }
}

// ---------------------------------------------------------------------------
// Persistent GRU scan. 128 blocks = 4 batch-groups x 32 j-tiles, 512 threads.
// jg = tid&7 (j pair), bg = (tid>>3)&7 (batch pair), ks = tid>>6 (k-split 8).
// h is staged into SMEM *pre-duplicated* ([h,h] pairs) in a 36-floats-per-16k
// group layout -> one LDS.128 delivers two packed f32x2 operands, no splats,
// and both staging STS and dot LDS are bank-conflict-free.
// hcol(k) = 36*(k>>4) + 2*(k&15)   (dup index = hcol, hcol+1)
// ---------------------------------------------------------------------------
#define HS_PITCH 1156   // 32 groups * 36 + pad

struct ScanSmem {
    float ws[3][8][1028];     // weights, j-pair interleaved: [gate][jp][k*2+p]
    float hs[16][HS_PITCH];   // duplicated h tile
    float red[512][12];       // k-split partials (pitch 12 -> conflict-free f4)
    float bhs[48];
};

__global__ void __launch_bounds__(512, 1)
scan_kernel(const float* __restrict__ Whh, const float* __restrict__ bhh,
            const float* __restrict__ xp, float* __restrict__ hseq)
{
    extern __shared__ ScanSmem smem[];
    ScanSmem& s = smem[0];

    const int tid = threadIdx.x;
    const int jg  = tid & 7;
    const int bg  = (tid >> 3) & 7;
    const int ks  = tid >> 6;
    const int bt  = blockIdx.x >> 5;
    const int jt  = blockIdx.x & 31;
    const int b0  = bt * 16;
    const int j0  = jt * 16;

    unsigned* cnt = &g_cnt4[bt * 32];
    unsigned* gen = &g_gen4[bt * 32];

    unsigned base_cnt = 0, base_gen = 0;
    if (tid == 0) {
        base_cnt = ld_acq(cnt) & ~(unsigned)(CNT_PER_LAUNCH - 1);
        base_gen = ld_acq(gen);
        base_gen -= base_gen % T_SZ;
    }

    // Resident weights: 48 rows x 512, pair-interleaved over j.
    for (int i = tid; i < 48 * 128; i += 512) {
        const int rl = i >> 7, k4 = i & 127;
        const int gg = rl >> 4, jj = rl & 15;
        float4 v = *(const float4*)(Whh + (size_t)(gg * H_SZ + j0 + jj) * H_SZ + k4 * 4);
        const int jp = jj >> 1, p = jj & 1;
        float* w = &s.ws[gg][jp][0];
        w[(k4 * 4 + 0) * 2 + p] = v.x;
        w[(k4 * 4 + 1) * 2 + p] = v.y;
        w[(k4 * 4 + 2) * 2 + p] = v.z;
        w[(k4 * 4 + 3) * 2 + p] = v.w;
    }
    if (tid < 48) s.bhs[tid] = bhh[(tid >> 4) * H_SZ + j0 + (tid & 15)];
    __syncthreads();

    for (int t = 0; t < T_SZ; t++) {
        // ---- finalizer xp prefetch (overlaps the staging below)
        float2 xv[2][3];
        if (ks == 0) {
#pragma unroll
            for (int b = 0; b < 2; b++) {
                const size_t row = ((size_t)(b0 + bg * 2 + b) * T_SZ + t) * G3_SZ;
#pragma unroll
                for (int g = 0; g < 3; g++)
                    xv[b][g] = *(const float2*)(xp + row + g * H_SZ + j0 + jg * 2);
            }
        }

        // ---- stage h_{t-1} duplicated (16 rows x 512 k -> 36-per-16k layout)
        if (t == 0) {
            float4 z = make_float4(0.f, 0.f, 0.f, 0.f);
            for (int i = tid; i < 16 * HS_PITCH / 4; i += 512)
                ((float4*)&s.hs[0][0])[i] = z;
        } else {
            float4 v[4];
#pragma unroll
            for (int u = 0; u < 4; u++) {
                const int i = tid + u * 512;
                const int b = i >> 7, k4 = i & 127;
                v[u] = *(const float4*)(hseq + ((size_t)(b0 + b) * T_SZ + (t - 1)) * H_SZ + k4 * 4);
            }
#pragma unroll
            for (int u = 0; u < 4; u++) {
                const int i = tid + u * 512;
                const int b = i >> 7, k4 = i & 127;
                float* d = &s.hs[b][36 * (k4 >> 2) + 8 * (k4 & 3)];
                ((float4*)d)[0] = make_float4(v[u].x, v[u].x, v[u].y, v[u].y);
                ((float4*)d)[1] = make_float4(v[u].z, v[u].z, v[u].w, v[u].w);
            }
        }
        __syncthreads();

        // ---- partial dots over this thread's 64 k's (4 k per c-iter)
        u64 acc[2][3];
#pragma unroll
        for (int b = 0; b < 2; b++)
#pragma unroll
            for (int g = 0; g < 3; g++) acc[b][g] = 0ull;

        {
            const float* h0p = &s.hs[bg * 2 + 0][144 * ks];
            const float* h1p = &s.hs[bg * 2 + 1][144 * ks];
            const float* wr  = &s.ws[0][jg][ks * 128];
            const float* wz  = &s.ws[1][jg][ks * 128];
            const float* wn  = &s.ws[2][jg][ks * 128];
#pragma unroll
            for (int c = 0; c < 16; c++) {
                const int ho = 36 * (c >> 2) + 8 * (c & 3);
                const int wo = c * 8;
                ulonglong2 hA = *(const ulonglong2*)(h0p + ho);      // k0,k1 dup
                ulonglong2 hB = *(const ulonglong2*)(h0p + ho + 4);  // k2,k3 dup
                ulonglong2 hC = *(const ulonglong2*)(h1p + ho);
                ulonglong2 hD = *(const ulonglong2*)(h1p + ho + 4);
                ulonglong2 rA = *(const ulonglong2*)(wr + wo);
                ulonglong2 rB = *(const ulonglong2*)(wr + wo + 4);
                ulonglong2 zA = *(const ulonglong2*)(wz + wo);
                ulonglong2 zB = *(const ulonglong2*)(wz + wo + 4);
                ulonglong2 nA = *(const ulonglong2*)(wn + wo);
                ulonglong2 nB = *(const ulonglong2*)(wn + wo + 4);
                fma2(acc[0][0], hA.x, rA.x); fma2(acc[0][0], hA.y, rA.y);
                fma2(acc[0][0], hB.x, rB.x); fma2(acc[0][0], hB.y, rB.y);
                fma2(acc[0][1], hA.x, zA.x); fma2(acc[0][1], hA.y, zA.y);
                fma2(acc[0][1], hB.x, zB.x); fma2(acc[0][1], hB.y, zB.y);
                fma2(acc[0][2], hA.x, nA.x); fma2(acc[0][2], hA.y, nA.y);
                fma2(acc[0][2], hB.x, nB.x); fma2(acc[0][2], hB.y, nB.y);
                fma2(acc[1][0], hC.x, rA.x); fma2(acc[1][0], hC.y, rA.y);
                fma2(acc[1][0], hD.x, rB.x); fma2(acc[1][0], hD.y, rB.y);
                fma2(acc[1][1], hC.x, zA.x); fma2(acc[1][1], hC.y, zA.y);
                fma2(acc[1][1], hD.x, zB.x); fma2(acc[1][1], hD.y, zB.y);
                fma2(acc[1][2], hC.x, nA.x); fma2(acc[1][2], hC.y, nA.y);
                fma2(acc[1][2], hD.x, nB.x); fma2(acc[1][2], hD.y, nB.y);
            }
        }

        // ---- write partials (pitch 12 -> conflict-free float4)
        {
            float v[12];
#pragma unroll
            for (int b = 0; b < 2; b++)
#pragma unroll
                for (int g = 0; g < 3; g++) {
                    float2 p = unpack2(acc[b][g]);
                    v[b * 6 + g * 2 + 0] = p.x;
                    v[b * 6 + g * 2 + 1] = p.y;
                }
            float* rp = &s.red[tid][0];
            *(float4*)(rp + 0) = make_float4(v[0], v[1], v[2], v[3]);
            *(float4*)(rp + 4) = make_float4(v[4], v[5], v[6], v[7]);
            *(float4*)(rp + 8) = make_float4(v[8], v[9], v[10], v[11]);
        }
        __syncthreads();

        // ---- finalize: tid < 64 sums 8 k-slices, gates, stores h_t
        if (ks == 0) {
            float4 t0 = make_float4(0.f, 0.f, 0.f, 0.f), t1 = t0, t2 = t0;
#pragma unroll
            for (int sidx = 0; sidx < 8; sidx++) {
                const float* rp = &s.red[tid + sidx * 64][0];
                float4 a = *(const float4*)(rp + 0);
                float4 b = *(const float4*)(rp + 4);
                float4 c = *(const float4*)(rp + 8);
                t0.x += a.x; t0.y += a.y; t0.z += a.z; t0.w += a.w;
                t1.x += b.x; t1.y += b.y; t1.z += b.z; t1.w += b.w;
                t2.x += c.x; t2.y += c.y; t2.z += c.z; t2.w += c.w;
            }
            float tot[12] = {t0.x, t0.y, t0.z, t0.w, t1.x, t1.y, t1.z, t1.w,
                             t2.x, t2.y, t2.z, t2.w};
            const int jl0 = jg * 2;
#pragma unroll
            for (int b = 0; b < 2; b++) {
                const int bl = bg * 2 + b;
                float2 hv;
#pragma unroll
                for (int p = 0; p < 2; p++) {
                    const int jl = jl0 + p;
                    float dr = tot[b * 6 + 0 + p];
                    float dz = tot[b * 6 + 2 + p];
                    float dn = tot[b * 6 + 4 + p];
                    float xr = (p == 0) ? xv[b][0].x : xv[b][0].y;
                    float xz = (p == 0) ? xv[b][1].x : xv[b][1].y;
                    float xn = (p == 0) ? xv[b][2].x : xv[b][2].y;
                    float rg = 1.f / (1.f + __expf(-(xr + dr + s.bhs[jl])));
                    float zg = 1.f / (1.f + __expf(-(xz + dz + s.bhs[16 + jl])));
                    float ng = tanhf(xn + rg * (dn + s.bhs[32 + jl]));
                    float hp = s.hs[bl][36 * jt + 2 * jl];     // duplicated index
                    float h  = (1.f - zg) * ng + zg * hp;
                    if (p == 0) hv.x = h; else hv.y = h;
                }
                *(float2*)(hseq + ((size_t)(b0 + bl) * T_SZ + t) * H_SZ + j0 + jl0) = hv;
            }
        }

        // ---- group barrier: acq_rel arrive, release publish, acquire spin
        __syncthreads();
        if (tid == 0) {
            unsigned ticket = atom_inc_acqrel(cnt) - base_cnt;
            const unsigned bar = (unsigned)t + 1u;
            if (ticket == bar * GRP_BLKS - 1u) {
                red_inc_release(gen);
            } else {
                const unsigned tgt = base_gen + bar;
                while ((int)(ld_acq(gen) - tgt) < 0) { }
            }
        }
        __syncthreads();
    }
}

// ---------------------------------------------------------------------------
// Launch
// ---------------------------------------------------------------------------
extern "C" void kernel_launch(void* const* d_in, const int* in_sizes, int n_in,
                              void* d_out, int out_size)
{
    (void)in_sizes; (void)n_in; (void)out_size;
    const float* x    = (const float*)d_in[0];
    const float* Wih0 = (const float*)d_in[1];
    const float* Whh0 = (const float*)d_in[2];
    const float* bih0 = (const float*)d_in[3];
    const float* bhh0 = (const float*)d_in[4];
    const float* Wih1 = (const float*)d_in[5];
    const float* Whh1 = (const float*)d_in[6];
    const float* bih1 = (const float*)d_in[7];
    const float* bhh1 = (const float*)d_in[8];
    const float* Wih2 = (const float*)d_in[9];
    const float* Whh2 = (const float*)d_in[10];
    const float* bih2 = (const float*)d_in[11];
    const float* bhh2 = (const float*)d_in[12];
    const float* Wout = (const float*)d_in[13];
    const float* bout = (const float*)d_in[14];
    float* out = (float*)d_out;

    cudaFuncSetAttribute(scan_kernel, cudaFuncAttributeMaxDynamicSharedMemorySize,
                         (int)sizeof(ScanSmem));

    void *xp_v = nullptr, *hs_v = nullptr;
    cudaGetSymbolAddress(&xp_v, g_xp);
    cudaGetSymbolAddress(&hs_v, g_hseq);
    float* xpd = (float*)xp_v;
    float* hs  = (float*)hs_v;

    const dim3 gblk(256), sblk(512);
    const dim3 g_proj(G3_SZ / 128, M_SZ / 128);
    const dim3 g_head(O_SZ / 128,  M_SZ / 128);
    const size_t scan_smem = sizeof(ScanSmem);

    gemm_bias_kernel<<<g_proj, gblk>>>(x,  Wih0, bih0, xpd, M_SZ, G3_SZ, F_SZ);
    scan_kernel<<<SCAN_NBLK, sblk, scan_smem>>>(Whh0, bhh0, xpd, hs);
    gemm_bias_kernel<<<g_proj, gblk>>>(hs, Wih1, bih1, xpd, M_SZ, G3_SZ, H_SZ);
    scan_kernel<<<SCAN_NBLK, sblk, scan_smem>>>(Whh1, bhh1, xpd, hs);
    gemm_bias_kernel<<<g_proj, gblk>>>(hs, Wih2, bih2, xpd, M_SZ, G3_SZ, H_SZ);
    scan_kernel<<<SCAN_NBLK, sblk, scan_smem>>>(Whh2, bhh2, xpd, hs);
    gemm_bias_kernel<<<g_head, gblk>>>(hs, Wout, bout, out, M_SZ, O_SZ, H_SZ);
}

// round 5
// speedup vs baseline: 1.2170x; 1.2170x over previous
#include <cuda_runtime.h>

// ---------------------------------------------------------------------------
// 3-layer GRU + linear head. B=64, T=512, F=128, H=512, 3H=1536, O=128.
// ---------------------------------------------------------------------------
#define B_SZ   64
#define T_SZ   512
#define F_SZ   128
#define H_SZ   512
#define G3_SZ  1536
#define O_SZ   128
#define M_SZ   (B_SZ * T_SZ)

#define SCAN_NBLK  128
#define GRP_BLKS   32

typedef unsigned long long u64;

__device__ __forceinline__ u64 splat2(float x) {
    u64 r; asm("mov.b64 %0, {%1, %1};" : "=l"(r) : "f"(x)); return r;
}
__device__ __forceinline__ void fma2(u64 &d, u64 a, u64 b) {
    asm("fma.rn.f32x2 %0, %1, %2, %0;" : "+l"(d) : "l"(a), "l"(b));
}
__device__ __forceinline__ float2 unpack2(u64 v) {
    float2 f; asm("mov.b64 {%0, %1}, %2;" : "=f"(f.x), "=f"(f.y) : "l"(v)); return f;
}
__device__ __forceinline__ unsigned ld_acq(const unsigned* p) {
    unsigned v; asm volatile("ld.global.acquire.gpu.u32 %0, [%1];" : "=r"(v) : "l"(p) : "memory"); return v;
}
__device__ __forceinline__ void st_rel(unsigned* p, unsigned v) {
    asm volatile("st.global.release.gpu.u32 [%0], %1;" :: "l"(p), "r"(v) : "memory");
}

// ---------------------------------------------------------------------------
// Scratch (device globals -- allocation-free per harness rules)
// ---------------------------------------------------------------------------
__device__ float    g_xp[(size_t)M_SZ * G3_SZ];
__device__ float    g_hseq[(size_t)M_SZ * H_SZ];
__device__ unsigned g_flags[4][32];   // per-block arrival step counters (one line per group)
__device__ unsigned g_genf[4][32];    // generation per group at [g][0], groups 128B apart

// ---------------------------------------------------------------------------
// GEMM: C[M,N] = A[M,K] @ W[N,K]^T + bias[N].  128x128x16 tile, f32x2 FMA,
// register double-buffered gmem loads.
// ---------------------------------------------------------------------------
__global__ void __launch_bounds__(256)
gemm_bias_kernel(const float* __restrict__ A, const float* __restrict__ W,
                 const float* __restrict__ bias, float* __restrict__ C,
                 int M, int N, int K)
{
    __shared__ float As[16][132];
    __shared__ float Ws[16][132];

    const int tid = threadIdx.x;
    const int tx  = tid & 15;
    const int ty  = tid >> 4;
    const int m0  = blockIdx.y * 128;
    const int n0  = blockIdx.x * 128;

    u64 acc[8][4];
#pragma unroll
    for (int i = 0; i < 8; i++)
#pragma unroll
        for (int j = 0; j < 4; j++) acc[i][j] = 0ull;

    const int lr = tid >> 2;
    const int lk = (tid & 3) * 4;

    float4 pa[2], pw[2];
#pragma unroll
    for (int h = 0; h < 2; h++) {
        const int row = lr + h * 64;
        pa[h] = *(const float4*)(A + (size_t)(m0 + row) * K + lk);
        pw[h] = *(const float4*)(W + (size_t)(n0 + row) * K + lk);
    }

    for (int k0 = 0; k0 < K; k0 += 16) {
#pragma unroll
        for (int h = 0; h < 2; h++) {
            const int row = lr + h * 64;
            As[lk + 0][row] = pa[h].x; As[lk + 1][row] = pa[h].y;
            As[lk + 2][row] = pa[h].z; As[lk + 3][row] = pa[h].w;
            Ws[lk + 0][row] = pw[h].x; Ws[lk + 1][row] = pw[h].y;
            Ws[lk + 2][row] = pw[h].z; Ws[lk + 3][row] = pw[h].w;
        }
        __syncthreads();
        if (k0 + 16 < K) {
#pragma unroll
            for (int h = 0; h < 2; h++) {
                const int row = lr + h * 64;
                pa[h] = *(const float4*)(A + (size_t)(m0 + row) * K + k0 + 16 + lk);
                pw[h] = *(const float4*)(W + (size_t)(n0 + row) * K + k0 + 16 + lk);
            }
        }
#pragma unroll
        for (int k = 0; k < 16; k++) {
            float4 a0 = *(const float4*)&As[k][ty * 8];
            float4 a1 = *(const float4*)&As[k][ty * 8 + 4];
            ulonglong2 w01 = *(const ulonglong2*)&Ws[k][tx * 8];
            ulonglong2 w23 = *(const ulonglong2*)&Ws[k][tx * 8 + 4];
            float av[8] = {a0.x, a0.y, a0.z, a0.w, a1.x, a1.y, a1.z, a1.w};
#pragma unroll
            for (int i = 0; i < 8; i++) {
                u64 as = splat2(av[i]);
                fma2(acc[i][0], as, w01.x);
                fma2(acc[i][1], as, w01.y);
                fma2(acc[i][2], as, w23.x);
                fma2(acc[i][3], as, w23.y);
            }
        }
        __syncthreads();
    }

#pragma unroll
    for (int i = 0; i < 8; i++) {
        const int m = m0 + ty * 8 + i;
        float* crow = C + (size_t)m * N + n0 + tx * 8;
#pragma unroll
        for (int j = 0; j < 4; j++) {
            float2 v = unpack2(acc[i][j]);
            const int n = n0 + tx * 8 + j * 2;
            crow[j * 2 + 0] = v.x + bias[n + 0];
            crow[j * 2 + 1] = v.y + bias[n + 1];
        }
    }
}

// ---------------------------------------------------------------------------
// Persistent GRU scan. 128 blocks = 4 batch-groups x 32 j-tiles, 512 threads.
// Thread mapping: jg = tid&7 (j pair), bg = (tid>>3)&3 (batch quad),
// ks = tid>>5 (k-split 16, 32 k's each; ks == warp id).
// Micro-tile per thread: 4 batches x 2 j x 3 gates (12 packed f32x2 accs).
// Whh tile (96KB, j-pair interleaved) SMEM-resident for all 512 steps.
// Barrier: per-block flag st.release + leader-warp parallel poll + gen publish.
// ---------------------------------------------------------------------------
struct ScanSmem {
    float    ws[3][8][1028];   // [gate][jpair][k*2+p]
    float    hs[16][516];      // h_{t-1} tile
    float    red[512][26];     // 24 partials per thread, pitch 26 (2-way max)
    float    bhs[48];
    unsigned baseu[2];
};

__global__ void __launch_bounds__(512, 1)
scan_kernel(const float* __restrict__ Whh, const float* __restrict__ bhh,
            const float* __restrict__ xp, float* __restrict__ hseq)
{
    extern __shared__ ScanSmem smem[];
    ScanSmem& s = smem[0];

    const int tid = threadIdx.x;
    const int jg  = tid & 7;
    const int bg  = (tid >> 3) & 3;
    const int ks  = tid >> 5;
    const int bt  = blockIdx.x >> 5;
    const int jt  = blockIdx.x & 31;
    const int b0  = bt * 16;
    const int j0  = jt * 16;

    if (tid == 0) {
        s.baseu[0] = ld_acq(&g_flags[bt][jt]);   // own flag (all group flags equal here)
        s.baseu[1] = ld_acq(&g_genf[bt][0]);
    }

    // Resident weights: 48 rows x 512, pair-interleaved over j.
    for (int i = tid; i < 48 * 128; i += 512) {
        const int rl = i >> 7, k4 = i & 127;
        const int gg = rl >> 4, jj = rl & 15;
        float4 v = *(const float4*)(Whh + (size_t)(gg * H_SZ + j0 + jj) * H_SZ + k4 * 4);
        const int jp = jj >> 1, p = jj & 1;
        float* w = &s.ws[gg][jp][0];
        w[(k4 * 4 + 0) * 2 + p] = v.x;
        w[(k4 * 4 + 1) * 2 + p] = v.y;
        w[(k4 * 4 + 2) * 2 + p] = v.z;
        w[(k4 * 4 + 3) * 2 + p] = v.w;
    }
    if (tid < 48) s.bhs[tid] = bhh[(tid >> 4) * H_SZ + j0 + (tid & 15)];
    __syncthreads();

    const unsigned base_flag = s.baseu[0];
    const unsigned base_gen  = s.baseu[1];

    // Finalizer identity (tid < 128): 1 batch x 2 j each.
    const int fb  = tid >> 5;        // batch member within quad (0..3)
    const int fi5 = tid & 31;        // bg_f*8 + jg_f
    const int fbg = fi5 >> 3;
    const int fjg = fi5 & 7;
    const int fbl = fbg * 4 + fb;    // local batch 0..15
    const int fjl0 = fjg * 2;

    // xp prefetch for t = 0
    float2 xv[3];
    if (tid < 128) {
        const size_t row = ((size_t)(b0 + fbl) * T_SZ + 0) * G3_SZ;
#pragma unroll
        for (int g = 0; g < 3; g++)
            xv[g] = *(const float2*)(xp + row + g * H_SZ + j0 + fjl0);
    }

    for (int t = 0; t < T_SZ; t++) {
        // ---- stage h_{t-1} (16 x 512)
        if (t == 0) {
            float4 z = make_float4(0.f, 0.f, 0.f, 0.f);
            for (int i = tid; i < 16 * 129; i += 512)
                ((float4*)&s.hs[0][0])[i] = z;
        } else {
#pragma unroll
            for (int u = 0; u < 4; u++) {
                const int i = tid + u * 512;
                const int b = i >> 7, k4 = i & 127;
                float4 v = *(const float4*)(hseq + ((size_t)(b0 + b) * T_SZ + (t - 1)) * H_SZ + k4 * 4);
                *(float4*)&s.hs[b][k4 * 4] = v;
            }
        }
        __syncthreads();

        // ---- partial dots: 4b x 2j x 3g over this thread's 32 k's
        u64 acc[4][3];
#pragma unroll
        for (int b = 0; b < 4; b++)
#pragma unroll
            for (int g = 0; g < 3; g++) acc[b][g] = 0ull;

        {
            const float* wr = &s.ws[0][jg][ks * 64];
            const float* wz = &s.ws[1][jg][ks * 64];
            const float* wn = &s.ws[2][jg][ks * 64];
            const float* hb = &s.hs[bg * 4][ks * 32];
#pragma unroll 2
            for (int c = 0; c < 8; c++) {
                ulonglong2 rA = *(const ulonglong2*)(wr + c * 8);
                ulonglong2 rB = *(const ulonglong2*)(wr + c * 8 + 4);
                ulonglong2 zA = *(const ulonglong2*)(wz + c * 8);
                ulonglong2 zB = *(const ulonglong2*)(wz + c * 8 + 4);
                ulonglong2 nA = *(const ulonglong2*)(wn + c * 8);
                ulonglong2 nB = *(const ulonglong2*)(wn + c * 8 + 4);
#pragma unroll
                for (int b = 0; b < 4; b++) {
                    float4 h = *(const float4*)(hb + b * 516 + c * 4);
                    u64 a0 = splat2(h.x), a1 = splat2(h.y);
                    u64 a2 = splat2(h.z), a3 = splat2(h.w);
                    fma2(acc[b][0], a0, rA.x); fma2(acc[b][0], a1, rA.y);
                    fma2(acc[b][0], a2, rB.x); fma2(acc[b][0], a3, rB.y);
                    fma2(acc[b][1], a0, zA.x); fma2(acc[b][1], a1, zA.y);
                    fma2(acc[b][1], a2, zB.x); fma2(acc[b][1], a3, zB.y);
                    fma2(acc[b][2], a0, nA.x); fma2(acc[b][2], a1, nA.y);
                    fma2(acc[b][2], a2, nB.x); fma2(acc[b][2], a3, nB.y);
                }
            }
        }

        // ---- write partials: [b][g][p] order, 12 x STS.64
        {
            float* rp = &s.red[tid][0];
#pragma unroll
            for (int b = 0; b < 4; b++)
#pragma unroll
                for (int g = 0; g < 3; g++)
                    *(float2*)(rp + b * 6 + g * 2) = unpack2(acc[b][g]);
        }
        __syncthreads();

        // ---- finalize: tid < 128, each 1 batch x 2 j; sum 16 k-slices
        if (tid < 128) {
            float2 t0 = make_float2(0.f, 0.f), t1 = t0, t2 = t0;
#pragma unroll
            for (int sdx = 0; sdx < 16; sdx++) {
                const float* rp = &s.red[sdx * 32 + fi5][fb * 6];
                float2 a = *(const float2*)(rp + 0);
                float2 b = *(const float2*)(rp + 2);
                float2 c = *(const float2*)(rp + 4);
                t0.x += a.x; t0.y += a.y;
                t1.x += b.x; t1.y += b.y;
                t2.x += c.x; t2.y += c.y;
            }
            float2 hv;
#pragma unroll
            for (int p = 0; p < 2; p++) {
                const int jl = fjl0 + p;
                float dr = (p == 0) ? t0.x : t0.y;
                float dz = (p == 0) ? t1.x : t1.y;
                float dn = (p == 0) ? t2.x : t2.y;
                float xr = (p == 0) ? xv[0].x : xv[0].y;
                float xz = (p == 0) ? xv[1].x : xv[1].y;
                float xn = (p == 0) ? xv[2].x : xv[2].y;
                float rg = 1.f / (1.f + __expf(-(xr + dr + s.bhs[jl])));
                float zg = 1.f / (1.f + __expf(-(xz + dz + s.bhs[16 + jl])));
                float ng = tanhf(xn + rg * (dn + s.bhs[32 + jl]));
                float hp = s.hs[fbl][j0 + jl];
                float h  = (1.f - zg) * ng + zg * hp;
                if (p == 0) hv.x = h; else hv.y = h;
            }
            *(float2*)(hseq + ((size_t)(b0 + fbl) * T_SZ + t) * H_SZ + j0 + fjl0) = hv;

            // prefetch xp for next step (independent of barrier)
            const int tn = (t + 1 < T_SZ) ? t + 1 : t;
            const size_t row = ((size_t)(b0 + fbl) * T_SZ + tn) * G3_SZ;
#pragma unroll
            for (int g = 0; g < 3; g++)
                xv[g] = *(const float2*)(xp + row + g * H_SZ + j0 + fjl0);
        }

        // ---- group barrier: flag publish, leader-warp parallel poll, gen publish
        __syncthreads();
        {
            const unsigned tgt = base_flag + (unsigned)t + 1u;
            if (tid == 0) st_rel(&g_flags[bt][jt], tgt);
            if (jt == 0) {
                if (tid < 32) {
                    while ((int)(ld_acq(&g_flags[bt][tid]) - tgt) < 0) { }
                    __syncwarp();
                    if (tid == 0) st_rel(&g_genf[bt][0], base_gen + (unsigned)t + 1u);
                }
            } else if (tid == 0) {
                const unsigned gt = base_gen + (unsigned)t + 1u;
                while ((int)(ld_acq(&g_genf[bt][0]) - gt) < 0) { }
            }
        }
        __syncthreads();
    }
}

// ---------------------------------------------------------------------------
// Launch
// ---------------------------------------------------------------------------
extern "C" void kernel_launch(void* const* d_in, const int* in_sizes, int n_in,
                              void* d_out, int out_size)
{
    (void)in_sizes; (void)n_in; (void)out_size;
    const float* x    = (const float*)d_in[0];
    const float* Wih0 = (const float*)d_in[1];
    const float* Whh0 = (const float*)d_in[2];
    const float* bih0 = (const float*)d_in[3];
    const float* bhh0 = (const float*)d_in[4];
    const float* Wih1 = (const float*)d_in[5];
    const float* Whh1 = (const float*)d_in[6];
    const float* bih1 = (const float*)d_in[7];
    const float* bhh1 = (const float*)d_in[8];
    const float* Wih2 = (const float*)d_in[9];
    const float* Whh2 = (const float*)d_in[10];
    const float* bih2 = (const float*)d_in[11];
    const float* bhh2 = (const float*)d_in[12];
    const float* Wout = (const float*)d_in[13];
    const float* bout = (const float*)d_in[14];
    float* out = (float*)d_out;

    cudaFuncSetAttribute(scan_kernel, cudaFuncAttributeMaxDynamicSharedMemorySize,
                         (int)sizeof(ScanSmem));

    void *xp_v = nullptr, *hs_v = nullptr;
    cudaGetSymbolAddress(&xp_v, g_xp);
    cudaGetSymbolAddress(&hs_v, g_hseq);
    float* xpd = (float*)xp_v;
    float* hs  = (float*)hs_v;

    const dim3 gblk(256), sblk(512);
    const dim3 g_proj(G3_SZ / 128, M_SZ / 128);
    const dim3 g_head(O_SZ / 128,  M_SZ / 128);
    const size_t scan_smem = sizeof(ScanSmem);

    gemm_bias_kernel<<<g_proj, gblk>>>(x,  Wih0, bih0, xpd, M_SZ, G3_SZ, F_SZ);
    scan_kernel<<<SCAN_NBLK, sblk, scan_smem>>>(Whh0, bhh0, xpd, hs);
    gemm_bias_kernel<<<g_proj, gblk>>>(hs, Wih1, bih1, xpd, M_SZ, G3_SZ, H_SZ);
    scan_kernel<<<SCAN_NBLK, sblk, scan_smem>>>(Whh1, bhh1, xpd, hs);
    gemm_bias_kernel<<<g_proj, gblk>>>(hs, Wih2, bih2, xpd, M_SZ, G3_SZ, H_SZ);
    scan_kernel<<<SCAN_NBLK, sblk, scan_smem>>>(Whh2, bhh2, xpd, hs);
    gemm_bias_kernel<<<g_head, gblk>>>(hs, Wout, bout, out, M_SZ, O_SZ, H_SZ);
}